// round 8
// baseline (speedup 1.0000x reference)
#include <cuda_runtime.h>

#define BB 2
#define KK 33
#define NN 50000
#define EE 800000
#define RR 200
#define DD 64
#define LL 3
#define NROWS (BB*NN)          /* 100000 */
#define NWORDS (NROWS/32)      /* 3125, exact */
#define TABW (NN*2/32)         /* 3125 */
#define GRID 148
#define BLK 256
#define NTHREADS (GRID*BLK)    /* 37888 */
#define NWARPS (NTHREADS/32)   /* 1184 */
#define SC_ITERS ((EE/4 + NTHREADS - 1) / NTHREADS)  /* 6 */

__device__ __align__(16) float g_x[NROWS*DD];
__device__ __align__(16) float g_agg[NROWS*DD];   // invariant: zero at phase entry
__device__ unsigned g_xmask[NWORDS];
__device__ unsigned g_amask[NWORDS];              // invariant: zero at phase entry
__device__ unsigned g_tab[TABW];                  // 2 bits/node, == xmask content
__device__ int      g_worklist[NROWS];
__device__ int      g_nwork[LL];
__device__ float g_query[BB*DD];
__device__ int   g_h0[BB];
__device__ float g_zv[LL][DD];
__device__ int   g_zfl[LL];
__device__ int   g_b64;

// software grid barrier state
__device__ unsigned g_bara = 0;
__device__ volatile unsigned g_barg = 0;

__device__ __forceinline__ void gridbar() {
    __syncthreads();
    if (threadIdx.x == 0) {
        unsigned gen = g_barg;            // stable between barriers
        __threadfence();
        if (atomicAdd(&g_bara, 1u) == gridDim.x - 1u) {
            g_bara = 0;
            __threadfence();
            g_barg = gen + 1u;            // release
        } else {
            while (g_barg == gen) __nanosleep(32);
        }
        __threadfence();
    }
    __syncthreads();
}

__device__ __forceinline__ int clampi(int v, int hi) {
    return v < 0 ? 0 : (v >= hi ? hi - 1 : v);
}
// bit-interleave: bit i of x -> bit 2i
__device__ __forceinline__ unsigned ileave16(unsigned x) {
    x = (x | (x << 8)) & 0x00FF00FFu;
    x = (x | (x << 4)) & 0x0F0F0F0Fu;
    x = (x | (x << 2)) & 0x33333333u;
    x = (x | (x << 1)) & 0x55555555u;
    return x;
}

__global__ void __launch_bounds__(BLK, 1)
k_main(const float* __restrict__ rel,
       const float* __restrict__ layer_w,
       const float* __restrict__ layer_b,
       const float* __restrict__ ln_g,
       const float* __restrict__ ln_b,
       const float* __restrict__ w1,
       const float* __restrict__ b1,
       const float* __restrict__ w2,
       const float* __restrict__ b2,
       const void*  __restrict__ batch,
       const int*   __restrict__ edge_index,
       const int*   __restrict__ etype,
       float*       __restrict__ out)
{
    __shared__ float s_W[2*DD*DD];    // 32KB: current layer's weights
    __shared__ float s_sb[LL][DD];
    __shared__ float s_mv[LL][2];
    __shared__ int   s_flag;
    __shared__ float s_feat[2*DD];
    __shared__ float s_hs[DD];

    const int tid   = threadIdx.x;
    const int gid   = blockIdx.x * BLK + tid;
    const int lane  = tid & 31;
    const int gwarp = (blockIdx.x * BLK + tid) >> 5;

    // ---------------- P0: sparse clean (old xmask marks dirty x rows) -----
    for (int w = gwarp; w < NWORDS; w += NWARPS) {
        unsigned m = g_xmask[w];
        if (m) {
            unsigned mm = m;
            while (mm) {
                int j = __ffs(mm) - 1; mm &= mm - 1;
                int row = w * 32 + j;
                ((float2*)g_x)[(size_t)row*32 + lane] = make_float2(0.f, 0.f);
            }
            if (lane == 0) g_xmask[w] = 0u;
        }
        if (lane == 0) g_tab[w] = 0u;
    }
    if (gid < LL) { g_zfl[gid] = 0; g_nwork[gid] = 0; }
    gridbar();

    // ---------------- P1: setup (block 0) ---------------------------------
    if (blockIdx.x == 0) {
        if (tid == 0) s_flag = 0;
        __syncthreads();
        const int* bw = (const int*)batch;
        if (tid < 99) {                       // odd words 1,3,...,197
            if (bw[2*tid + 1] != 0) atomicOr(&s_flag, 1);
        }
        __syncthreads();
        int is64 = !s_flag;
        if (tid == 0) g_b64 = is64;
        if (tid < DD) {
            int d = tid;
            for (int b = 0; b < BB; b++) {
                int i0 = (b*KK)*3;
                int h0 = clampi(is64 ? (int)((const long long*)batch)[i0    ] : bw[i0    ], NN);
                int r0 = clampi(is64 ? (int)((const long long*)batch)[i0 + 2] : bw[i0 + 2], RR);
                float q = rel[((size_t)b*RR + r0)*DD + d];
                g_query[b*DD + d] = q;
                g_x[((size_t)(b*NN + h0))*DD + d] = q;
                if (d == 0) {
                    g_h0[b] = h0;
                    int row = b*NN + h0;
                    atomicOr(&g_xmask[row >> 5], 1u << (row & 31));
                    atomicOr(&g_tab[h0 >> 4], 1u << (((h0 & 15) << 1) + b));
                }
            }
        }
        if (tid < LL*DD) {
            int l = tid >> 6, d = tid & 63;
            s_sb[l][d] = layer_b[l*DD + d];
        }
        __syncthreads();
        if (tid < LL) {
            float su = 0.f, sq = 0.f;
            for (int i = 0; i < DD; i++) { float v = s_sb[tid][i]; su += v; sq += v*v; }
            float mu = su * (1.f/DD);
            s_mv[tid][0] = mu;
            s_mv[tid][1] = sq * (1.f/DD) - mu*mu;
        }
        __syncthreads();
        if (tid < LL*DD) {
            int l = tid >> 6, d = tid & 63;
            float v = s_sb[l][d];
            float z = (v - s_mv[l][0]) * rsqrtf(s_mv[l][1] + 1e-5f) * ln_g[l*DD + d] + ln_b[l*DD + d];
            z = fmaxf(z, 0.f);
            g_zv[l][d] = z;
            if (z != 0.f) atomicOr(&g_zfl[l], 1);
        }
    }
    gridbar();

    // ---------------- layers ----------------------------------------------
    for (int l = 0; l < LL; l++) {
        // stage this layer's weights into smem (overlaps with scatter)
        {
            const float4* Wsrc = (const float4*)(layer_w + (size_t)l*2*DD*DD);
            float4* Wdst = (float4*)s_W;
            #pragma unroll
            for (int i = tid; i < 2*DD*DD/4; i += BLK) Wdst[i] = Wsrc[i];
        }
        // ---- scatter: agg[b,dst] += x[b,src] * rel[b,etype] --------------
        for (int it = 0; it < SC_ITERS; it++) {
            int idx  = gid + it * NTHREADS;
            int base = idx * 4;
            int4 s4 = make_int4(0, 0, 0, 0);
            unsigned pr0 = 0, pr1 = 0, pr2 = 0, pr3 = 0;
            if (base < EE) {
                s4 = ((const int4*)edge_index)[idx];
                pr0 = (g_tab[s4.x >> 4] >> ((s4.x & 15) << 1)) & 3u;
                pr1 = (g_tab[s4.y >> 4] >> ((s4.y & 15) << 1)) & 3u;
                pr2 = (g_tab[s4.z >> 4] >> ((s4.z & 15) << 1)) & 3u;
                pr3 = (g_tab[s4.w >> 4] >> ((s4.w & 15) << 1)) & 3u;
            }
            int srcs[4] = {s4.x, s4.y, s4.z, s4.w};
            unsigned prs[4] = {pr0, pr1, pr2, pr3};
            #pragma unroll
            for (int k = 0; k < 4; k++) {
                unsigned b0 = __ballot_sync(0xffffffffu, prs[k] & 1u);
                unsigned b1 = __ballot_sync(0xffffffffu, prs[k] & 2u);
                unsigned act = b0 | b1;
                while (act) {
                    int j = __ffs(act) - 1;
                    act &= act - 1;
                    int ej = __shfl_sync(0xffffffffu, base, j) + k;
                    int sj = __shfl_sync(0xffffffffu, srcs[k], j);
                    int dj = 0, tj = 0;
                    if (lane == j) { dj = edge_index[EE + ej]; tj = etype[ej]; }
                    dj = __shfl_sync(0xffffffffu, dj, j);
                    tj = __shfl_sync(0xffffffffu, tj, j);
                    #pragma unroll
                    for (int b = 0; b < BB; b++) {
                        unsigned bb = b ? b1 : b0;
                        if (!((bb >> j) & 1)) continue;   // uniform across warp
                        float2 xv = ((const float2*)g_x)[((size_t)(b*NN + sj))*32 + lane];
                        float2 rv = ((const float2*)rel)[((size_t)(b*RR + tj))*32 + lane];
                        float* ap = &g_agg[((size_t)(b*NN + dj))*DD + 2*lane];
                        atomicAdd(ap,     xv.x * rv.x);
                        atomicAdd(ap + 1, xv.y * rv.y);
                        if (lane == 0) {
                            int row = b*NN + dj;
                            atomicOr(&g_amask[row >> 5], 1u << (row & 31));
                        }
                    }
                }
            }
        }
        gridbar();

        // ---- compact: merge masks, delta-update tab, build worklist ------
        if (gid < NWORDS) {
            unsigned xm = g_xmask[gid];
            unsigned am = g_amask[gid];
            unsigned act = xm | am;
            if (am) {
                g_amask[gid] = 0u;
                unsigned delta = am & ~xm;
                if (delta) {
                    g_xmask[gid] = act;
                    #pragma unroll
                    for (int h = 0; h < 2; h++) {       // 16-row halves
                        unsigned bits = (delta >> (16*h)) & 0xFFFFu;
                        if (!bits) continue;
                        int rowbase = gid * 32 + 16*h;  // multiple of 16
                        if (rowbase < NN)
                            atomicOr(&g_tab[rowbase >> 4], ileave16(bits));
                        else {
                            int node = rowbase - NN;    // also multiple of 16
                            atomicOr(&g_tab[node >> 4], ileave16(bits) << 1);
                        }
                    }
                }
            }
            if (act) {
                int n = __popc(act);
                int base = atomicAdd(&g_nwork[l], n);
                unsigned mm = act;
                while (mm) {
                    int j = __ffs(mm) - 1; mm &= mm - 1;
                    g_worklist[base++] = gid * 32 + j;
                }
            }
        }
        gridbar();

        // ---- update: one warp per worklist row, weights from smem --------
        {
            int cnt = g_nwork[l];
            float bj0  = layer_b[l*DD + 2*lane], bj1  = layer_b[l*DD + 2*lane + 1];
            float gj0  = ln_g[l*DD + 2*lane],    gj1  = ln_g[l*DD + 2*lane + 1];
            float btj0 = ln_b[l*DD + 2*lane],    btj1 = ln_b[l*DD + 2*lane + 1];
            for (int i = gwarp; i < cnt; i += NWARPS) {
                int row = g_worklist[i];
                int b   = row / NN;
                int n   = row - b * NN;
                float2 a2 = ((float2*)g_agg)[(size_t)row*32 + lane];
                float2 x2 = ((float2*)g_x)[(size_t)row*32 + lane];
                if (n == g_h0[b]) {
                    a2.x += g_query[b*DD + 2*lane];
                    a2.y += g_query[b*DD + 2*lane + 1];
                }
                float acc0 = bj0, acc1 = bj1;
                #pragma unroll 8
                for (int ii = 0; ii < 32; ii++) {       // cat[0:64] = agg
                    float cx = __shfl_sync(0xffffffffu, a2.x, ii);
                    float cy = __shfl_sync(0xffffffffu, a2.y, ii);
                    float2 w0 = ((const float2*)(s_W + (2*ii    )*DD))[lane];
                    float2 w1v = ((const float2*)(s_W + (2*ii + 1)*DD))[lane];
                    acc0 += cx*w0.x + cy*w1v.x;
                    acc1 += cx*w0.y + cy*w1v.y;
                }
                #pragma unroll 8
                for (int ii = 0; ii < 32; ii++) {       // cat[64:128] = x
                    float cx = __shfl_sync(0xffffffffu, x2.x, ii);
                    float cy = __shfl_sync(0xffffffffu, x2.y, ii);
                    float2 w0 = ((const float2*)(s_W + (64 + 2*ii    )*DD))[lane];
                    float2 w1v = ((const float2*)(s_W + (64 + 2*ii + 1)*DD))[lane];
                    acc0 += cx*w0.x + cy*w1v.x;
                    acc1 += cx*w0.y + cy*w1v.y;
                }
                float su = acc0 + acc1;
                float sq = acc0*acc0 + acc1*acc1;
                #pragma unroll
                for (int o = 16; o; o >>= 1) {
                    su += __shfl_xor_sync(0xffffffffu, su, o);
                    sq += __shfl_xor_sync(0xffffffffu, sq, o);
                }
                float mu  = su * (1.f/DD);
                float var = sq * (1.f/DD) - mu*mu;
                float rs  = rsqrtf(var + 1e-5f);
                float u0 = fmaxf((acc0 - mu)*rs*gj0 + btj0, 0.f);
                float u1 = fmaxf((acc1 - mu)*rs*gj1 + btj1, 0.f);
                x2.x += u0; x2.y += u1;
                ((float2*)g_x)[(size_t)row*32 + lane] = x2;
                ((float2*)g_agg)[(size_t)row*32 + lane] = make_float2(0.f, 0.f);
            }
            // cold path: dense z_l densify (z_l == 0 for these inputs)
            if (l < LL - 1 && g_zfl[l]) {
                for (int r = gid; r < NROWS; r += NTHREADS) {
                    if (!((g_xmask[r >> 5] >> (r & 31)) & 1)) {
                        for (int d = 0; d < DD; d++)
                            g_x[(size_t)r*DD + d] += g_zv[l][d];
                        atomicOr(&g_xmask[r >> 5], 1u << (r & 31));
                    }
                }
                for (int r = gid; r < TABW; r += NTHREADS)
                    g_tab[r] = 0xFFFFFFFFu;
            }
        }
        gridbar();
    }

    // ---------------- score ------------------------------------------------
    if (blockIdx.x < BB*KK) {
        int b = blockIdx.x / KK, k = blockIdx.x % KK;
        if (tid < DD) {
            int ti = (b*KK + k)*3 + 1;
            int t  = clampi(g_b64 ? (int)((const long long*)batch)[ti]
                                  : ((const int*)batch)[ti], NN);
            int row = b*NN + t;
            float f = g_x[(size_t)row*DD + tid];
            if (g_zfl[LL-1] && !((g_xmask[row >> 5] >> (row & 31)) & 1))
                f += g_zv[LL-1][tid];
            s_feat[tid]      = f;
            s_feat[DD + tid] = g_query[b*DD + tid];
        }
        __syncthreads();
        if (tid < DD) {
            float acc = b1[tid];
            #pragma unroll 8
            for (int i = 0; i < 2*DD; i++) acc += s_feat[i] * w1[i*DD + tid];
            float h = fmaxf(acc, 0.f);
            s_hs[tid] = h * w2[tid];
        }
        __syncthreads();
        if (tid == 0) {
            float s = b2[0];
            for (int i = 0; i < DD; i++) s += s_hs[i];
            out[b*KK + k] = s;
        }
    }
}

// ---------------------------------------------------------------------------
extern "C" void kernel_launch(void* const* d_in, const int* in_sizes, int n_in,
                              void* d_out, int out_size) {
    const float* rel      = (const float*)d_in[0];
    const float* layer_w  = (const float*)d_in[1];
    const float* layer_b  = (const float*)d_in[2];
    const float* ln_g     = (const float*)d_in[3];
    const float* ln_b     = (const float*)d_in[4];
    const float* mlp_w1   = (const float*)d_in[5];
    const float* mlp_b1   = (const float*)d_in[6];
    const float* mlp_w2   = (const float*)d_in[7];
    const float* mlp_b2   = (const float*)d_in[8];
    const void*  batch    = d_in[9];
    const int*   edge_idx = (const int*)d_in[10];
    const int*   edge_typ = (const int*)d_in[11];
    float*       out      = (float*)d_out;

    k_main<<<GRID, BLK>>>(rel, layer_w, layer_b, ln_g, ln_b,
                          mlp_w1, mlp_b1, mlp_w2, mlp_b2,
                          batch, edge_idx, edge_typ, out);
}

// round 9
// speedup vs baseline: 1.1719x; 1.1719x over previous
#include <cuda_runtime.h>

#define BB 2
#define KK 33
#define NN 50000
#define EE 800000
#define RR 200
#define DD 64
#define LL 3
#define NROWS (BB*NN)          /* 100000 */
#define NWORDS (NROWS/32)      /* 3125, exact */
#define TABW (NN*2/32)         /* 3125 */
#define GRID 148
#define BLK 512
#define NTHREADS (GRID*BLK)    /* 75776 */
#define NWARPS (NTHREADS/32)   /* 2368 */
#define WPB ((NWORDS + GRID - 1)/GRID)   /* 22 mask words per block */
#define SC_ITERS ((EE/4 + NTHREADS - 1) / NTHREADS)  /* 3 */

__device__ __align__(16) float g_x[NROWS*DD];
__device__ __align__(16) float g_agg[NROWS*DD];   // invariant: zero at phase entry
__device__ unsigned g_xmask[NWORDS];
__device__ unsigned g_amask[NWORDS];              // invariant: zero at phase entry
__device__ unsigned g_tab[TABW];                  // 2 bits/node, mirrors xmask
__device__ float g_query[BB*DD];
__device__ int   g_h0[BB];
__device__ float g_zv[LL][DD];
__device__ int   g_zfl[LL];
__device__ int   g_b64;

// software grid barrier state
__device__ unsigned g_bara = 0;
__device__ volatile unsigned g_barg = 0;

__device__ __forceinline__ void gridbar() {
    __syncthreads();
    if (threadIdx.x == 0) {
        unsigned gen = g_barg;            // stable between barriers
        __threadfence();
        if (atomicAdd(&g_bara, 1u) == gridDim.x - 1u) {
            g_bara = 0;
            __threadfence();
            g_barg = gen + 1u;            // release
        } else {
            while (g_barg == gen) __nanosleep(32);
        }
        __threadfence();
    }
    __syncthreads();
}

__device__ __forceinline__ int clampi(int v, int hi) {
    return v < 0 ? 0 : (v >= hi ? hi - 1 : v);
}
// bit-interleave: bit i of x -> bit 2i
__device__ __forceinline__ unsigned ileave16(unsigned x) {
    x = (x | (x << 8)) & 0x00FF00FFu;
    x = (x | (x << 4)) & 0x0F0F0F0Fu;
    x = (x | (x << 2)) & 0x33333333u;
    x = (x | (x << 1)) & 0x55555555u;
    return x;
}

__global__ void __launch_bounds__(BLK, 1)
k_main(const float* __restrict__ rel,
       const float* __restrict__ layer_w,
       const float* __restrict__ layer_b,
       const float* __restrict__ ln_g,
       const float* __restrict__ ln_b,
       const float* __restrict__ w1,
       const float* __restrict__ b1,
       const float* __restrict__ w2,
       const float* __restrict__ b2,
       const void*  __restrict__ batch,
       const int*   __restrict__ edge_index,
       const int*   __restrict__ etype,
       float*       __restrict__ out)
{
    __shared__ float s_W[2*DD*DD];    // 32KB: current layer's weights
    __shared__ int   s_wl[WPB*32];    // block-local row worklist (<=704)
    __shared__ int   s_cnt;
    __shared__ float s_sb[LL][DD];
    __shared__ float s_mv[LL][2];
    __shared__ int   s_flag;
    __shared__ float s_feat[2*DD];
    __shared__ float s_hs[DD];

    const int tid   = threadIdx.x;
    const int gid   = blockIdx.x * BLK + tid;
    const int lane  = tid & 31;
    const int bwarp = tid >> 5;                       // warp in block (0..15)
    const int gwarp = gid >> 5;

    // ---------------- P0: sparse clean (old xmask marks dirty x rows) -----
    for (int w = gwarp; w < NWORDS; w += NWARPS) {
        unsigned m = g_xmask[w];
        if (m) {
            unsigned mm = m;
            while (mm) {
                int j = __ffs(mm) - 1; mm &= mm - 1;
                int row = w * 32 + j;
                ((float2*)g_x)[(size_t)row*32 + lane] = make_float2(0.f, 0.f);
            }
            if (lane == 0) g_xmask[w] = 0u;
        }
        if (lane == 0) g_tab[w] = 0u;
    }
    if (gid < LL) g_zfl[gid] = 0;
    gridbar();

    // ---------------- P1: setup (block 0) ---------------------------------
    if (blockIdx.x == 0) {
        if (tid == 0) s_flag = 0;
        __syncthreads();
        const int* bw = (const int*)batch;
        if (tid < 99) {                       // odd words 1,3,...,197
            if (bw[2*tid + 1] != 0) atomicOr(&s_flag, 1);
        }
        __syncthreads();
        int is64 = !s_flag;
        if (tid == 0) g_b64 = is64;
        if (tid < DD) {
            int d = tid;
            for (int b = 0; b < BB; b++) {
                int i0 = (b*KK)*3;
                int h0 = clampi(is64 ? (int)((const long long*)batch)[i0    ] : bw[i0    ], NN);
                int r0 = clampi(is64 ? (int)((const long long*)batch)[i0 + 2] : bw[i0 + 2], RR);
                float q = rel[((size_t)b*RR + r0)*DD + d];
                g_query[b*DD + d] = q;
                g_x[((size_t)(b*NN + h0))*DD + d] = q;
                if (d == 0) {
                    g_h0[b] = h0;
                    int row = b*NN + h0;
                    atomicOr(&g_xmask[row >> 5], 1u << (row & 31));
                    atomicOr(&g_tab[h0 >> 4], 1u << (((h0 & 15) << 1) + b));
                }
            }
        }
        if (tid < LL*DD) {
            int l = tid >> 6, d = tid & 63;
            s_sb[l][d] = layer_b[l*DD + d];
        }
        __syncthreads();
        if (tid < LL) {
            float su = 0.f, sq = 0.f;
            for (int i = 0; i < DD; i++) { float v = s_sb[tid][i]; su += v; sq += v*v; }
            float mu = su * (1.f/DD);
            s_mv[tid][0] = mu;
            s_mv[tid][1] = sq * (1.f/DD) - mu*mu;
        }
        __syncthreads();
        if (tid < LL*DD) {
            int l = tid >> 6, d = tid & 63;
            float v = s_sb[l][d];
            float z = (v - s_mv[l][0]) * rsqrtf(s_mv[l][1] + 1e-5f) * ln_g[l*DD + d] + ln_b[l*DD + d];
            z = fmaxf(z, 0.f);
            g_zv[l][d] = z;
            if (z != 0.f) atomicOr(&g_zfl[l], 1);
        }
    }
    gridbar();

    // ---------------- layers ----------------------------------------------
    for (int l = 0; l < LL; l++) {
        // stage this layer's weights into smem (overlaps with scatter)
        {
            const float4* Wsrc = (const float4*)(layer_w + (size_t)l*2*DD*DD);
            float4* Wdst = (float4*)s_W;
            #pragma unroll
            for (int i = tid; i < 2*DD*DD/4; i += BLK) Wdst[i] = Wsrc[i];
            if (tid == 0) s_cnt = 0;
        }
        // ---- scatter: agg[b,dst] += x[b,src] * rel[b,etype] --------------
        for (int it = 0; it < SC_ITERS; it++) {
            int idx  = gid + it * NTHREADS;
            int base = idx * 4;
            int4 s4 = make_int4(0, 0, 0, 0);
            unsigned pr0 = 0, pr1 = 0, pr2 = 0, pr3 = 0;
            if (base < EE) {
                s4 = ((const int4*)edge_index)[idx];
                pr0 = (g_tab[s4.x >> 4] >> ((s4.x & 15) << 1)) & 3u;
                pr1 = (g_tab[s4.y >> 4] >> ((s4.y & 15) << 1)) & 3u;
                pr2 = (g_tab[s4.z >> 4] >> ((s4.z & 15) << 1)) & 3u;
                pr3 = (g_tab[s4.w >> 4] >> ((s4.w & 15) << 1)) & 3u;
            }
            int srcs[4] = {s4.x, s4.y, s4.z, s4.w};
            unsigned prs[4] = {pr0, pr1, pr2, pr3};
            #pragma unroll
            for (int k = 0; k < 4; k++) {
                unsigned b0 = __ballot_sync(0xffffffffu, prs[k] & 1u);
                unsigned b1 = __ballot_sync(0xffffffffu, prs[k] & 2u);
                unsigned act = b0 | b1;
                while (act) {
                    int j = __ffs(act) - 1;
                    act &= act - 1;
                    int ej = __shfl_sync(0xffffffffu, base, j) + k;
                    int sj = __shfl_sync(0xffffffffu, srcs[k], j);
                    int dj = 0, tj = 0;
                    if (lane == j) { dj = edge_index[EE + ej]; tj = etype[ej]; }
                    dj = __shfl_sync(0xffffffffu, dj, j);
                    tj = __shfl_sync(0xffffffffu, tj, j);
                    #pragma unroll
                    for (int b = 0; b < BB; b++) {
                        unsigned bb = b ? b1 : b0;
                        if (!((bb >> j) & 1)) continue;   // uniform across warp
                        float2 xv = ((const float2*)g_x)[((size_t)(b*NN + sj))*32 + lane];
                        float2 rv = ((const float2*)rel)[((size_t)(b*RR + tj))*32 + lane];
                        float* ap = &g_agg[((size_t)(b*NN + dj))*DD + 2*lane];
                        atomicAdd(ap,     xv.x * rv.x);
                        atomicAdd(ap + 1, xv.y * rv.y);
                        if (lane == 0) {
                            int row = b*NN + dj;
                            atomicOr(&g_amask[row >> 5], 1u << (row & 31));
                        }
                    }
                }
            }
        }
        gridbar();

        // ---- fused compact + update over this block's 22 mask words ------
        if (tid < WPB) {
            int w = blockIdx.x * WPB + tid;
            if (w < NWORDS) {
                unsigned xm = g_xmask[w];
                unsigned am = g_amask[w];
                unsigned act = xm | am;
                if (am) {
                    g_amask[w] = 0u;
                    unsigned delta = am & ~xm;
                    if (delta) {
                        g_xmask[w] = act;
                        #pragma unroll
                        for (int h = 0; h < 2; h++) {       // 16-row halves
                            unsigned bits = (delta >> (16*h)) & 0xFFFFu;
                            if (!bits) continue;
                            int rowbase = w * 32 + 16*h;    // multiple of 16
                            if (rowbase < NN)
                                atomicOr(&g_tab[rowbase >> 4], ileave16(bits));
                            else {
                                int node = rowbase - NN;    // NN%16==0
                                atomicOr(&g_tab[node >> 4], ileave16(bits) << 1);
                            }
                        }
                    }
                }
                if (act) {
                    int n = __popc(act);
                    int base = atomicAdd(&s_cnt, n);
                    unsigned mm = act;
                    while (mm) {
                        int j = __ffs(mm) - 1; mm &= mm - 1;
                        s_wl[base++] = w * 32 + j;
                    }
                }
            }
        }
        __syncthreads();

        {
            int cnt = s_cnt;
            float bj0  = layer_b[l*DD + 2*lane], bj1  = layer_b[l*DD + 2*lane + 1];
            float gj0  = ln_g[l*DD + 2*lane],    gj1  = ln_g[l*DD + 2*lane + 1];
            float btj0 = ln_b[l*DD + 2*lane],    btj1 = ln_b[l*DD + 2*lane + 1];
            for (int i = bwarp; i < cnt; i += BLK/32) {
                int row = s_wl[i];
                int b   = row / NN;
                int n   = row - b * NN;
                float2 a2 = ((float2*)g_agg)[(size_t)row*32 + lane];
                float2 x2 = ((float2*)g_x)[(size_t)row*32 + lane];
                if (n == g_h0[b]) {
                    a2.x += g_query[b*DD + 2*lane];
                    a2.y += g_query[b*DD + 2*lane + 1];
                }
                float acc0 = bj0, acc1 = bj1;
                #pragma unroll 8
                for (int ii = 0; ii < 32; ii++) {       // cat[0:64] = agg
                    float cx = __shfl_sync(0xffffffffu, a2.x, ii);
                    float cy = __shfl_sync(0xffffffffu, a2.y, ii);
                    float2 w0 = ((const float2*)(s_W + (2*ii    )*DD))[lane];
                    float2 w1v = ((const float2*)(s_W + (2*ii + 1)*DD))[lane];
                    acc0 += cx*w0.x + cy*w1v.x;
                    acc1 += cx*w0.y + cy*w1v.y;
                }
                #pragma unroll 8
                for (int ii = 0; ii < 32; ii++) {       // cat[64:128] = x
                    float cx = __shfl_sync(0xffffffffu, x2.x, ii);
                    float cy = __shfl_sync(0xffffffffu, x2.y, ii);
                    float2 w0 = ((const float2*)(s_W + (64 + 2*ii    )*DD))[lane];
                    float2 w1v = ((const float2*)(s_W + (64 + 2*ii + 1)*DD))[lane];
                    acc0 += cx*w0.x + cy*w1v.x;
                    acc1 += cx*w0.y + cy*w1v.y;
                }
                float su = acc0 + acc1;
                float sq = acc0*acc0 + acc1*acc1;
                #pragma unroll
                for (int o = 16; o; o >>= 1) {
                    su += __shfl_xor_sync(0xffffffffu, su, o);
                    sq += __shfl_xor_sync(0xffffffffu, sq, o);
                }
                float mu  = su * (1.f/DD);
                float var = sq * (1.f/DD) - mu*mu;
                float rs  = rsqrtf(var + 1e-5f);
                float u0 = fmaxf((acc0 - mu)*rs*gj0 + btj0, 0.f);
                float u1 = fmaxf((acc1 - mu)*rs*gj1 + btj1, 0.f);
                x2.x += u0; x2.y += u1;
                ((float2*)g_x)[(size_t)row*32 + lane] = x2;
                ((float2*)g_agg)[(size_t)row*32 + lane] = make_float2(0.f, 0.f);
            }
            // cold path: dense z_l densify (z_l == 0 for these inputs)
            if (l < LL - 1 && g_zfl[l]) {
                for (int r = gid; r < NROWS; r += NTHREADS) {
                    if (!((g_xmask[r >> 5] >> (r & 31)) & 1)) {
                        for (int d = 0; d < DD; d++)
                            g_x[(size_t)r*DD + d] += g_zv[l][d];
                        atomicOr(&g_xmask[r >> 5], 1u << (r & 31));
                    }
                }
                for (int r = gid; r < TABW; r += NTHREADS)
                    g_tab[r] = 0xFFFFFFFFu;
            }
        }
        gridbar();
    }

    // ---------------- score ------------------------------------------------
    if (blockIdx.x < BB*KK) {
        int b = blockIdx.x / KK, k = blockIdx.x % KK;
        if (tid < DD) {
            int ti = (b*KK + k)*3 + 1;
            int t  = clampi(g_b64 ? (int)((const long long*)batch)[ti]
                                  : ((const int*)batch)[ti], NN);
            int row = b*NN + t;
            float f = g_x[(size_t)row*DD + tid];
            if (g_zfl[LL-1] && !((g_xmask[row >> 5] >> (row & 31)) & 1))
                f += g_zv[LL-1][tid];
            s_feat[tid]      = f;
            s_feat[DD + tid] = g_query[b*DD + tid];
        }
        __syncthreads();
        if (tid < DD) {
            float acc = b1[tid];
            #pragma unroll 8
            for (int i = 0; i < 2*DD; i++) acc += s_feat[i] * w1[i*DD + tid];
            float h = fmaxf(acc, 0.f);
            s_hs[tid] = h * w2[tid];
        }
        __syncthreads();
        if (tid == 0) {
            float s = b2[0];
            for (int i = 0; i < DD; i++) s += s_hs[i];
            out[b*KK + k] = s;
        }
    }
}

// ---------------------------------------------------------------------------
extern "C" void kernel_launch(void* const* d_in, const int* in_sizes, int n_in,
                              void* d_out, int out_size) {
    const float* rel      = (const float*)d_in[0];
    const float* layer_w  = (const float*)d_in[1];
    const float* layer_b  = (const float*)d_in[2];
    const float* ln_g     = (const float*)d_in[3];
    const float* ln_b     = (const float*)d_in[4];
    const float* mlp_w1   = (const float*)d_in[5];
    const float* mlp_b1   = (const float*)d_in[6];
    const float* mlp_w2   = (const float*)d_in[7];
    const float* mlp_b2   = (const float*)d_in[8];
    const void*  batch    = d_in[9];
    const int*   edge_idx = (const int*)d_in[10];
    const int*   edge_typ = (const int*)d_in[11];
    float*       out      = (float*)d_out;

    k_main<<<GRID, BLK>>>(rel, layer_w, layer_b, ln_g, ln_b,
                          mlp_w1, mlp_b1, mlp_w2, mlp_b2,
                          batch, edge_idx, edge_typ, out);
}

// round 10
// speedup vs baseline: 1.2093x; 1.0319x over previous
#include <cuda_runtime.h>

#define BB 2
#define KK 33
#define NN 50000
#define EE 800000
#define RR 200
#define DD 64
#define LL 3
#define NROWS (BB*NN)          /* 100000 */
#define NWORDS (NROWS/32)      /* 3125, exact */
#define TABW (NN*2/32)         /* 3125 */
#define GRID 148
#define BLK 512
#define NTHREADS (GRID*BLK)    /* 75776 */
#define NWARPS (NTHREADS/32)   /* 2368 */
#define WPB ((NWORDS + GRID - 1)/GRID)   /* 22 mask words per block */
#define SC_ITERS 3             /* ceil(EE/4 / NTHREADS) */

__device__ __align__(16) float g_x[NROWS*DD];
__device__ __align__(16) float g_agg[NROWS*DD];   // invariant: zero at phase entry
__device__ unsigned g_xmask[NWORDS];
__device__ unsigned g_amask[NWORDS];              // invariant: zero at phase entry
__device__ unsigned g_tab[TABW];                  // 2 bits/node, mirrors xmask
__device__ float g_query[BB*DD];
__device__ int   g_h0[BB];
__device__ float g_zv[LL][DD];
__device__ int   g_zfl[LL];
__device__ int   g_b64;

// software grid barrier state
__device__ unsigned g_bara = 0;
__device__ volatile unsigned g_barg = 0;

__device__ __forceinline__ void gridbar() {
    __syncthreads();
    if (threadIdx.x == 0) {
        unsigned gen = g_barg;            // stable between barriers
        __threadfence();
        if (atomicAdd(&g_bara, 1u) == gridDim.x - 1u) {
            g_bara = 0;
            __threadfence();
            g_barg = gen + 1u;            // release
        } else {
            while (g_barg == gen) __nanosleep(32);
        }
        __threadfence();
    }
    __syncthreads();
}

__device__ __forceinline__ int clampi(int v, int hi) {
    return v < 0 ? 0 : (v >= hi ? hi - 1 : v);
}
// bit-interleave: bit i of x -> bit 2i
__device__ __forceinline__ unsigned ileave16(unsigned x) {
    x = (x | (x << 8)) & 0x00FF00FFu;
    x = (x | (x << 4)) & 0x0F0F0F0Fu;
    x = (x | (x << 2)) & 0x33333333u;
    x = (x | (x << 1)) & 0x55555555u;
    return x;
}

__global__ void __launch_bounds__(BLK, 1)
k_main(const float* __restrict__ rel,
       const float* __restrict__ layer_w,
       const float* __restrict__ layer_b,
       const float* __restrict__ ln_g,
       const float* __restrict__ ln_b,
       const float* __restrict__ w1,
       const float* __restrict__ b1,
       const float* __restrict__ w2,
       const float* __restrict__ b2,
       const void*  __restrict__ batch,
       const int*   __restrict__ edge_index,
       const int*   __restrict__ etype,
       float*       __restrict__ out)
{
    __shared__ float s_W[2*DD*DD];    // 32KB: current layer's weights
    __shared__ int   s_wl[WPB*32];    // block-local row worklist (<=704)
    __shared__ int   s_cnt;
    __shared__ float s_sb[LL][DD];
    __shared__ float s_mv[LL][2];
    __shared__ float s_feat[2*DD];
    __shared__ float s_hs[DD];

    const int tid   = threadIdx.x;
    const int gid   = blockIdx.x * BLK + tid;
    const int lane  = tid & 31;
    const int bwarp = tid >> 5;                       // warp in block (0..15)
    const int gwarp = gid >> 5;

    // ---------------- P0: sparse clean + distributed setup -----------------
    // Clean: old xmask marks dirty x rows; warp gwarp owns words
    // {gwarp, gwarp+NWARPS} exclusively.
    for (int w = gwarp; w < NWORDS; w += NWARPS) {
        unsigned m = g_xmask[w];
        if (m) {
            unsigned mm = m;
            while (mm) {
                int j = __ffs(mm) - 1; mm &= mm - 1;
                int row = w * 32 + j;
                ((float2*)g_x)[(size_t)row*32 + lane] = make_float2(0.f, 0.f);
            }
            if (lane == 0) g_xmask[w] = 0u;
        }
        if (lane == 0) g_tab[w] = 0u;
    }
    // Distributed setup: every warp computes is64 + h0/r0 (cached loads);
    // the warps that OWN h0's xmask word / tab word do the seeding — no
    // cross-warp race, no extra barrier.
    {
        const int* bw = (const int*)batch;
        const long long* bl64 = (const long long*)batch;
        int bad = 0;
        for (int i = lane; i < 99; i += 32)           // odd words 1..197
            if (bw[2*i + 1] != 0) bad = 1;
        int is64 = (__ballot_sync(0xffffffffu, bad) == 0);
        if (gwarp == 0 && lane == 0) g_b64 = is64;
        #pragma unroll
        for (int b = 0; b < BB; b++) {
            int i0 = (b*KK)*3;
            int h0 = clampi(is64 ? (int)bl64[i0    ] : bw[i0    ], NN);
            int r0 = clampi(is64 ? (int)bl64[i0 + 2] : bw[i0 + 2], RR);
            int row = b*NN + h0;
            int wx = row >> 5;
            if (wx % NWARPS == gwarp) {               // xmask/x/query owner
                float2 q = ((const float2*)rel)[((size_t)b*RR + r0)*32 + lane];
                ((float2*)g_x)[(size_t)row*32 + lane] = q;
                ((float2*)g_query)[b*32 + lane] = q;
                if (lane == 0) {
                    g_h0[b] = h0;
                    g_xmask[wx] |= 1u << (row & 31);  // exclusive owner
                }
            }
            int wt = h0 >> 4;
            if (wt % NWARPS == gwarp && lane == 0)    // tab owner
                atomicOr(&g_tab[wt], 1u << (((h0 & 15) << 1) + b));
        }
    }
    // z_l = relu(LN(layer_b[l])) — block 0, in parallel with other blocks
    if (blockIdx.x == 0 && tid < LL) g_zfl[tid] = 0;
    if (blockIdx.x == 0 && tid < LL*DD)
        s_sb[tid >> 6][tid & 63] = layer_b[tid];
    __syncthreads();
    if (blockIdx.x == 0 && tid < LL) {
        float su = 0.f, sq = 0.f;
        for (int i = 0; i < DD; i++) { float v = s_sb[tid][i]; su += v; sq += v*v; }
        float mu = su * (1.f/DD);
        s_mv[tid][0] = mu;
        s_mv[tid][1] = sq * (1.f/DD) - mu*mu;
    }
    __syncthreads();
    if (blockIdx.x == 0 && tid < LL*DD) {
        int l = tid >> 6, d = tid & 63;
        float v = s_sb[l][d];
        float z = (v - s_mv[l][0]) * rsqrtf(s_mv[l][1] + 1e-5f) * ln_g[tid] + ln_b[tid];
        z = fmaxf(z, 0.f);
        g_zv[l][d] = z;
        if (z != 0.f) atomicOr(&g_zfl[l], 1);
    }
    gridbar();

    // ---------------- layers ----------------------------------------------
    for (int l = 0; l < LL; l++) {
        // stage this layer's weights into smem (overlaps with scatter)
        {
            const float4* Wsrc = (const float4*)(layer_w + (size_t)l*2*DD*DD);
            float4* Wdst = (float4*)s_W;
            #pragma unroll
            for (int i = tid; i < 2*DD*DD/4; i += BLK) Wdst[i] = Wsrc[i];
            if (tid == 0) s_cnt = 0;
        }
        // ---- scatter: agg[b,dst] += x[b,src] * rel[b,etype] --------------
        // Pipelined: 3 independent int4 edge loads, then 12 independent tab
        // probes, then process (single early-exit ballot per 4-edge group).
        {
            int4 s4v[SC_ITERS];
            unsigned pk[SC_ITERS];
            #pragma unroll
            for (int it = 0; it < SC_ITERS; it++) {
                int idx = gid + it * NTHREADS;
                s4v[it] = (idx*4 < EE) ? ((const int4*)edge_index)[idx]
                                       : make_int4(0, 0, 0, 0);
            }
            #pragma unroll
            for (int it = 0; it < SC_ITERS; it++) {
                int idx = gid + it * NTHREADS;
                unsigned p = 0;
                if (idx*4 < EE) {
                    p  = ((g_tab[s4v[it].x >> 4] >> ((s4v[it].x & 15) << 1)) & 3u);
                    p |= ((g_tab[s4v[it].y >> 4] >> ((s4v[it].y & 15) << 1)) & 3u) << 2;
                    p |= ((g_tab[s4v[it].z >> 4] >> ((s4v[it].z & 15) << 1)) & 3u) << 4;
                    p |= ((g_tab[s4v[it].w >> 4] >> ((s4v[it].w & 15) << 1)) & 3u) << 6;
                }
                pk[it] = p;
            }
            #pragma unroll
            for (int it = 0; it < SC_ITERS; it++) {
                if (__ballot_sync(0xffffffffu, pk[it] != 0) == 0) continue;
                int base = (gid + it * NTHREADS) * 4;
                int srcs[4] = {s4v[it].x, s4v[it].y, s4v[it].z, s4v[it].w};
                #pragma unroll
                for (int k = 0; k < 4; k++) {
                    unsigned prk = (pk[it] >> (2*k)) & 3u;
                    unsigned b0 = __ballot_sync(0xffffffffu, prk & 1u);
                    unsigned b1 = __ballot_sync(0xffffffffu, prk & 2u);
                    unsigned act = b0 | b1;
                    while (act) {
                        int j = __ffs(act) - 1;
                        act &= act - 1;
                        int ej = __shfl_sync(0xffffffffu, base, j) + k;
                        int sj = __shfl_sync(0xffffffffu, srcs[k], j);
                        int dj = 0, tj = 0;
                        if (lane == j) { dj = edge_index[EE + ej]; tj = etype[ej]; }
                        dj = __shfl_sync(0xffffffffu, dj, j);
                        tj = __shfl_sync(0xffffffffu, tj, j);
                        #pragma unroll
                        for (int b = 0; b < BB; b++) {
                            unsigned bb = b ? b1 : b0;
                            if (!((bb >> j) & 1)) continue;   // uniform
                            float2 xv = ((const float2*)g_x)[((size_t)(b*NN + sj))*32 + lane];
                            float2 rv = ((const float2*)rel)[((size_t)(b*RR + tj))*32 + lane];
                            float* ap = &g_agg[((size_t)(b*NN + dj))*DD + 2*lane];
                            atomicAdd(ap,     xv.x * rv.x);
                            atomicAdd(ap + 1, xv.y * rv.y);
                            if (lane == 0) {
                                int row = b*NN + dj;
                                atomicOr(&g_amask[row >> 5], 1u << (row & 31));
                            }
                        }
                    }
                }
            }
        }
        gridbar();

        // ---- fused compact + update over this block's 22 mask words ------
        if (tid < WPB) {
            int w = blockIdx.x * WPB + tid;
            if (w < NWORDS) {
                unsigned xm = g_xmask[w];
                unsigned am = g_amask[w];
                unsigned act = xm | am;
                if (am) {
                    g_amask[w] = 0u;
                    unsigned delta = am & ~xm;
                    if (delta) {
                        g_xmask[w] = act;
                        #pragma unroll
                        for (int h = 0; h < 2; h++) {       // 16-row halves
                            unsigned bits = (delta >> (16*h)) & 0xFFFFu;
                            if (!bits) continue;
                            int rowbase = w * 32 + 16*h;    // multiple of 16
                            if (rowbase < NN)
                                atomicOr(&g_tab[rowbase >> 4], ileave16(bits));
                            else {
                                int node = rowbase - NN;    // NN%16==0
                                atomicOr(&g_tab[node >> 4], ileave16(bits) << 1);
                            }
                        }
                    }
                }
                if (act) {
                    int n = __popc(act);
                    int base = atomicAdd(&s_cnt, n);
                    unsigned mm = act;
                    while (mm) {
                        int j = __ffs(mm) - 1; mm &= mm - 1;
                        s_wl[base++] = w * 32 + j;
                    }
                }
            }
        }
        __syncthreads();

        {
            int cnt = s_cnt;
            float bj0  = layer_b[l*DD + 2*lane], bj1  = layer_b[l*DD + 2*lane + 1];
            float gj0  = ln_g[l*DD + 2*lane],    gj1  = ln_g[l*DD + 2*lane + 1];
            float btj0 = ln_b[l*DD + 2*lane],    btj1 = ln_b[l*DD + 2*lane + 1];
            for (int i = bwarp; i < cnt; i += BLK/32) {
                int row = s_wl[i];
                int b   = row / NN;
                int n   = row - b * NN;
                float2 a2 = ((float2*)g_agg)[(size_t)row*32 + lane];
                float2 x2 = ((float2*)g_x)[(size_t)row*32 + lane];
                if (n == g_h0[b]) {
                    a2.x += g_query[b*DD + 2*lane];
                    a2.y += g_query[b*DD + 2*lane + 1];
                }
                float acc0 = bj0, acc1 = bj1;
                #pragma unroll 8
                for (int ii = 0; ii < 32; ii++) {       // cat[0:64] = agg
                    float cx = __shfl_sync(0xffffffffu, a2.x, ii);
                    float cy = __shfl_sync(0xffffffffu, a2.y, ii);
                    float2 w0 = ((const float2*)(s_W + (2*ii    )*DD))[lane];
                    float2 w1v = ((const float2*)(s_W + (2*ii + 1)*DD))[lane];
                    acc0 += cx*w0.x + cy*w1v.x;
                    acc1 += cx*w0.y + cy*w1v.y;
                }
                #pragma unroll 8
                for (int ii = 0; ii < 32; ii++) {       // cat[64:128] = x
                    float cx = __shfl_sync(0xffffffffu, x2.x, ii);
                    float cy = __shfl_sync(0xffffffffu, x2.y, ii);
                    float2 w0 = ((const float2*)(s_W + (64 + 2*ii    )*DD))[lane];
                    float2 w1v = ((const float2*)(s_W + (64 + 2*ii + 1)*DD))[lane];
                    acc0 += cx*w0.x + cy*w1v.x;
                    acc1 += cx*w0.y + cy*w1v.y;
                }
                float su = acc0 + acc1;
                float sq = acc0*acc0 + acc1*acc1;
                #pragma unroll
                for (int o = 16; o; o >>= 1) {
                    su += __shfl_xor_sync(0xffffffffu, su, o);
                    sq += __shfl_xor_sync(0xffffffffu, sq, o);
                }
                float mu  = su * (1.f/DD);
                float var = sq * (1.f/DD) - mu*mu;
                float rs  = rsqrtf(var + 1e-5f);
                float u0 = fmaxf((acc0 - mu)*rs*gj0 + btj0, 0.f);
                float u1 = fmaxf((acc1 - mu)*rs*gj1 + btj1, 0.f);
                x2.x += u0; x2.y += u1;
                ((float2*)g_x)[(size_t)row*32 + lane] = x2;
                ((float2*)g_agg)[(size_t)row*32 + lane] = make_float2(0.f, 0.f);
            }
            // cold path: dense z_l densify (z_l == 0 for these inputs)
            if (l < LL - 1 && g_zfl[l]) {
                for (int r = gid; r < NROWS; r += NTHREADS) {
                    if (!((g_xmask[r >> 5] >> (r & 31)) & 1)) {
                        for (int d = 0; d < DD; d++)
                            g_x[(size_t)r*DD + d] += g_zv[l][d];
                        atomicOr(&g_xmask[r >> 5], 1u << (r & 31));
                    }
                }
                for (int r = gid; r < TABW; r += NTHREADS)
                    g_tab[r] = 0xFFFFFFFFu;
            }
        }
        gridbar();
    }

    // ---------------- score ------------------------------------------------
    if (blockIdx.x < BB*KK) {
        int b = blockIdx.x / KK, k = blockIdx.x % KK;
        if (tid < DD) {
            int ti = (b*KK + k)*3 + 1;
            int t  = clampi(g_b64 ? (int)((const long long*)batch)[ti]
                                  : ((const int*)batch)[ti], NN);
            int row = b*NN + t;
            float f = g_x[(size_t)row*DD + tid];
            if (g_zfl[LL-1] && !((g_xmask[row >> 5] >> (row & 31)) & 1))
                f += g_zv[LL-1][tid];
            s_feat[tid]      = f;
            s_feat[DD + tid] = g_query[b*DD + tid];
        }
        __syncthreads();
        if (tid < DD) {
            float acc = b1[tid];
            #pragma unroll 8
            for (int i = 0; i < 2*DD; i++) acc += s_feat[i] * w1[i*DD + tid];
            float h = fmaxf(acc, 0.f);
            s_hs[tid] = h * w2[tid];
        }
        __syncthreads();
        if (tid == 0) {
            float s = b2[0];
            for (int i = 0; i < DD; i++) s += s_hs[i];
            out[b*KK + k] = s;
        }
    }
}

// ---------------------------------------------------------------------------
extern "C" void kernel_launch(void* const* d_in, const int* in_sizes, int n_in,
                              void* d_out, int out_size) {
    const float* rel      = (const float*)d_in[0];
    const float* layer_w  = (const float*)d_in[1];
    const float* layer_b  = (const float*)d_in[2];
    const float* ln_g     = (const float*)d_in[3];
    const float* ln_b     = (const float*)d_in[4];
    const float* mlp_w1   = (const float*)d_in[5];
    const float* mlp_b1   = (const float*)d_in[6];
    const float* mlp_w2   = (const float*)d_in[7];
    const float* mlp_b2   = (const float*)d_in[8];
    const void*  batch    = d_in[9];
    const int*   edge_idx = (const int*)d_in[10];
    const int*   edge_typ = (const int*)d_in[11];
    float*       out      = (float*)d_out;

    k_main<<<GRID, BLK>>>(rel, layer_w, layer_b, ln_g, ln_b,
                          mlp_w1, mlp_b1, mlp_w2, mlp_b2,
                          batch, edge_idx, edge_typ, out);
}

// round 11
// speedup vs baseline: 1.2485x; 1.0325x over previous
#include <cuda_runtime.h>

#define BB 2
#define KK 33
#define NN 50000
#define EE 800000
#define RR 200
#define DD 64
#define LL 3
#define NROWS (BB*NN)          /* 100000 */
#define NWORDS (NROWS/32)      /* 3125, exact */
#define TABW (NN*2/32)         /* 3125 */
#define GRID 148
#define BLK 768
#define NTHREADS (GRID*BLK)    /* 113664 */
#define NWARPS (NTHREADS/32)   /* 3552 */
#define WPB ((NWORDS + GRID - 1)/GRID)   /* 22 mask words per block */
#define SC_ITERS 2             /* ceil((EE/4)/NTHREADS) */

__device__ __align__(16) float g_x[NROWS*DD];
__device__ __align__(16) float g_agg[NROWS*DD];   // invariant: zero at phase entry
__device__ unsigned g_xmask[NWORDS];
__device__ unsigned g_amask[NWORDS];              // invariant: zero at phase entry
__device__ unsigned g_tab[TABW];                  // 2 bits/node, mirrors xmask
__device__ float g_query[BB*DD];
__device__ int   g_h0[BB];
__device__ float g_zv[LL][DD];
__device__ int   g_zfl[LL];
__device__ int   g_b64;

// Tree grid barrier: per-block arrival slots + single release word.
// Generations are ABSOLUTE and monotone across launches/replays: each launch
// reads base = g_rel at entry and uses base+1..base+7. At launch entry,
// g_arrive[i] == g_rel == base (final state of previous launch; 0 initially),
// so no reset is ever needed and there is no reset race.
__device__ unsigned g_arrive[GRID];
__device__ volatile unsigned g_rel;

__device__ __forceinline__ void gridbar(unsigned target) {
    __syncthreads();
    if (blockIdx.x == 0) {
        int t = threadIdx.x;
        if (t > 0 && t < GRID) {
            volatile unsigned* a = (volatile unsigned*)&g_arrive[t];
            while (*a < target) __nanosleep(32);
        }
        __syncthreads();
        if (t == 0) { __threadfence(); g_rel = target; }
    } else {
        if (threadIdx.x == 0) {
            __threadfence();   // publish block's writes + flush L1
            ((volatile unsigned*)g_arrive)[blockIdx.x] = target;
            while (g_rel < target) __nanosleep(32);
        }
    }
    __syncthreads();
}

__device__ __forceinline__ int clampi(int v, int hi) {
    return v < 0 ? 0 : (v >= hi ? hi - 1 : v);
}
// bit-interleave: bit i of x -> bit 2i
__device__ __forceinline__ unsigned ileave16(unsigned x) {
    x = (x | (x << 8)) & 0x00FF00FFu;
    x = (x | (x << 4)) & 0x0F0F0F0Fu;
    x = (x | (x << 2)) & 0x33333333u;
    x = (x | (x << 1)) & 0x55555555u;
    return x;
}

__global__ void __launch_bounds__(BLK, 1)
k_main(const float* __restrict__ rel,
       const float* __restrict__ layer_w,
       const float* __restrict__ layer_b,
       const float* __restrict__ ln_g,
       const float* __restrict__ ln_b,
       const float* __restrict__ w1,
       const float* __restrict__ b1,
       const float* __restrict__ w2,
       const float* __restrict__ b2,
       const void*  __restrict__ batch,
       const int*   __restrict__ edge_index,
       const int*   __restrict__ etype,
       float*       __restrict__ out)
{
    __shared__ float s_W[2*DD*DD];    // 32KB: current layer's weights
    __shared__ int   s_wl[WPB*32];    // block-local row worklist (<=704)
    __shared__ int   s_cnt;
    __shared__ float s_sb[LL][DD];
    __shared__ float s_mv[LL][2];
    __shared__ float s_feat[2*DD];
    __shared__ float s_hs[DD];
    __shared__ unsigned s_base;

    const int tid   = threadIdx.x;
    const int gid   = blockIdx.x * BLK + tid;
    const int lane  = tid & 31;
    const int bwarp = tid >> 5;                       // warp in block (0..23)
    const int gwarp = gid >> 5;

    if (tid == 0) s_base = g_rel;     // barrier generation base for this launch
    __syncthreads();

    // ---------------- P0: sparse clean + distributed setup -----------------
    // Clean: old xmask marks dirty x rows; warp gwarp owns words
    // {gwarp, gwarp+NWARPS} exclusively.
    for (int w = gwarp; w < NWORDS; w += NWARPS) {
        unsigned m = g_xmask[w];
        if (m) {
            unsigned mm = m;
            while (mm) {
                int j = __ffs(mm) - 1; mm &= mm - 1;
                int row = w * 32 + j;
                ((float2*)g_x)[(size_t)row*32 + lane] = make_float2(0.f, 0.f);
            }
            if (lane == 0) g_xmask[w] = 0u;
        }
        if (lane == 0) g_tab[w] = 0u;
    }
    // Distributed setup: every warp computes is64 + h0/r0 (cached loads);
    // the warps that OWN h0's xmask word / tab word do the seeding — no
    // cross-warp race, no extra barrier.
    {
        const int* bw = (const int*)batch;
        const long long* bl64 = (const long long*)batch;
        int bad = 0;
        for (int i = lane; i < 99; i += 32)           // odd words 1..197
            if (bw[2*i + 1] != 0) bad = 1;
        int is64 = (__ballot_sync(0xffffffffu, bad) == 0);
        if (gwarp == 0 && lane == 0) g_b64 = is64;
        #pragma unroll
        for (int b = 0; b < BB; b++) {
            int i0 = (b*KK)*3;
            int h0 = clampi(is64 ? (int)bl64[i0    ] : bw[i0    ], NN);
            int r0 = clampi(is64 ? (int)bl64[i0 + 2] : bw[i0 + 2], RR);
            int row = b*NN + h0;
            int wx = row >> 5;
            if (wx % NWARPS == gwarp) {               // xmask/x/query owner
                float2 q = ((const float2*)rel)[((size_t)b*RR + r0)*32 + lane];
                ((float2*)g_x)[(size_t)row*32 + lane] = q;
                ((float2*)g_query)[b*32 + lane] = q;
                if (lane == 0) {
                    g_h0[b] = h0;
                    g_xmask[wx] |= 1u << (row & 31);  // exclusive owner
                }
            }
            int wt = h0 >> 4;
            if (wt % NWARPS == gwarp && lane == 0)    // tab owner
                atomicOr(&g_tab[wt], 1u << (((h0 & 15) << 1) + b));
        }
    }
    // z_l = relu(LN(layer_b[l])) — block 0, in parallel with other blocks
    if (blockIdx.x == 0 && tid < LL) g_zfl[tid] = 0;
    if (blockIdx.x == 0 && tid < LL*DD)
        s_sb[tid >> 6][tid & 63] = layer_b[tid];
    __syncthreads();
    if (blockIdx.x == 0 && tid < LL) {
        float su = 0.f, sq = 0.f;
        for (int i = 0; i < DD; i++) { float v = s_sb[tid][i]; su += v; sq += v*v; }
        float mu = su * (1.f/DD);
        s_mv[tid][0] = mu;
        s_mv[tid][1] = sq * (1.f/DD) - mu*mu;
    }
    __syncthreads();
    if (blockIdx.x == 0 && tid < LL*DD) {
        int l = tid >> 6, d = tid & 63;
        float v = s_sb[l][d];
        float z = (v - s_mv[l][0]) * rsqrtf(s_mv[l][1] + 1e-5f) * ln_g[tid] + ln_b[tid];
        z = fmaxf(z, 0.f);
        g_zv[l][d] = z;
        if (z != 0.f) atomicOr(&g_zfl[l], 1);
    }
    gridbar(s_base + 1);

    // ---------------- layers ----------------------------------------------
    for (int l = 0; l < LL; l++) {
        // stage this layer's weights into smem (overlaps with scatter)
        {
            const float4* Wsrc = (const float4*)(layer_w + (size_t)l*2*DD*DD);
            float4* Wdst = (float4*)s_W;
            for (int i = tid; i < 2*DD*DD/4; i += BLK) Wdst[i] = Wsrc[i];
            if (tid == 0) s_cnt = 0;
        }
        // ---- scatter: agg[b,dst] += x[b,src] * rel[b,etype] --------------
        // Pipelined: independent int4 edge loads, then independent tab
        // probes, then process (single early-exit ballot per 4-edge group).
        {
            int4 s4v[SC_ITERS];
            unsigned pk[SC_ITERS];
            #pragma unroll
            for (int it = 0; it < SC_ITERS; it++) {
                int idx = gid + it * NTHREADS;
                s4v[it] = (idx*4 < EE) ? ((const int4*)edge_index)[idx]
                                       : make_int4(0, 0, 0, 0);
            }
            #pragma unroll
            for (int it = 0; it < SC_ITERS; it++) {
                int idx = gid + it * NTHREADS;
                unsigned p = 0;
                if (idx*4 < EE) {
                    p  = ((g_tab[s4v[it].x >> 4] >> ((s4v[it].x & 15) << 1)) & 3u);
                    p |= ((g_tab[s4v[it].y >> 4] >> ((s4v[it].y & 15) << 1)) & 3u) << 2;
                    p |= ((g_tab[s4v[it].z >> 4] >> ((s4v[it].z & 15) << 1)) & 3u) << 4;
                    p |= ((g_tab[s4v[it].w >> 4] >> ((s4v[it].w & 15) << 1)) & 3u) << 6;
                }
                pk[it] = p;
            }
            #pragma unroll
            for (int it = 0; it < SC_ITERS; it++) {
                if (__ballot_sync(0xffffffffu, pk[it] != 0) == 0) continue;
                int base = (gid + it * NTHREADS) * 4;
                int srcs[4] = {s4v[it].x, s4v[it].y, s4v[it].z, s4v[it].w};
                #pragma unroll
                for (int k = 0; k < 4; k++) {
                    unsigned prk = (pk[it] >> (2*k)) & 3u;
                    unsigned b0 = __ballot_sync(0xffffffffu, prk & 1u);
                    unsigned b1 = __ballot_sync(0xffffffffu, prk & 2u);
                    unsigned act = b0 | b1;
                    while (act) {
                        int j = __ffs(act) - 1;
                        act &= act - 1;
                        int ej = __shfl_sync(0xffffffffu, base, j) + k;
                        int sj = __shfl_sync(0xffffffffu, srcs[k], j);
                        int dj = 0, tj = 0;
                        if (lane == j) { dj = edge_index[EE + ej]; tj = etype[ej]; }
                        dj = __shfl_sync(0xffffffffu, dj, j);
                        tj = __shfl_sync(0xffffffffu, tj, j);
                        #pragma unroll
                        for (int b = 0; b < BB; b++) {
                            unsigned bb = b ? b1 : b0;
                            if (!((bb >> j) & 1)) continue;   // uniform
                            float2 xv = ((const float2*)g_x)[((size_t)(b*NN + sj))*32 + lane];
                            float2 rv = ((const float2*)rel)[((size_t)(b*RR + tj))*32 + lane];
                            float* ap = &g_agg[((size_t)(b*NN + dj))*DD + 2*lane];
                            atomicAdd(ap,     xv.x * rv.x);
                            atomicAdd(ap + 1, xv.y * rv.y);
                            if (lane == 0) {
                                int row = b*NN + dj;
                                atomicOr(&g_amask[row >> 5], 1u << (row & 31));
                            }
                        }
                    }
                }
            }
        }
        gridbar(s_base + 2 + 2*l);

        // ---- fused compact + update over this block's 22 mask words ------
        if (tid < WPB) {
            int w = blockIdx.x * WPB + tid;
            if (w < NWORDS) {
                unsigned xm = g_xmask[w];
                unsigned am = g_amask[w];
                unsigned act = xm | am;
                if (am) {
                    g_amask[w] = 0u;
                    unsigned delta = am & ~xm;
                    if (delta) {
                        g_xmask[w] = act;
                        #pragma unroll
                        for (int h = 0; h < 2; h++) {       // 16-row halves
                            unsigned bits = (delta >> (16*h)) & 0xFFFFu;
                            if (!bits) continue;
                            int rowbase = w * 32 + 16*h;    // multiple of 16
                            if (rowbase < NN)
                                atomicOr(&g_tab[rowbase >> 4], ileave16(bits));
                            else {
                                int node = rowbase - NN;    // NN%16==0
                                atomicOr(&g_tab[node >> 4], ileave16(bits) << 1);
                            }
                        }
                    }
                }
                if (act) {
                    int n = __popc(act);
                    int base = atomicAdd(&s_cnt, n);
                    unsigned mm = act;
                    while (mm) {
                        int j = __ffs(mm) - 1; mm &= mm - 1;
                        s_wl[base++] = w * 32 + j;
                    }
                }
            }
        }
        __syncthreads();

        {
            int cnt = s_cnt;
            float bj0  = layer_b[l*DD + 2*lane], bj1  = layer_b[l*DD + 2*lane + 1];
            float gj0  = ln_g[l*DD + 2*lane],    gj1  = ln_g[l*DD + 2*lane + 1];
            float btj0 = ln_b[l*DD + 2*lane],    btj1 = ln_b[l*DD + 2*lane + 1];
            for (int i = bwarp; i < cnt; i += BLK/32) {
                int row = s_wl[i];
                int b   = row / NN;
                int n   = row - b * NN;
                float2 a2 = ((float2*)g_agg)[(size_t)row*32 + lane];
                float2 x2 = ((float2*)g_x)[(size_t)row*32 + lane];
                if (n == g_h0[b]) {
                    a2.x += g_query[b*DD + 2*lane];
                    a2.y += g_query[b*DD + 2*lane + 1];
                }
                float acc0 = bj0, acc1 = bj1;
                #pragma unroll 8
                for (int ii = 0; ii < 32; ii++) {       // cat[0:64] = agg
                    float cx = __shfl_sync(0xffffffffu, a2.x, ii);
                    float cy = __shfl_sync(0xffffffffu, a2.y, ii);
                    float2 w0 = ((const float2*)(s_W + (2*ii    )*DD))[lane];
                    float2 w1v = ((const float2*)(s_W + (2*ii + 1)*DD))[lane];
                    acc0 += cx*w0.x + cy*w1v.x;
                    acc1 += cx*w0.y + cy*w1v.y;
                }
                #pragma unroll 8
                for (int ii = 0; ii < 32; ii++) {       // cat[64:128] = x
                    float cx = __shfl_sync(0xffffffffu, x2.x, ii);
                    float cy = __shfl_sync(0xffffffffu, x2.y, ii);
                    float2 w0 = ((const float2*)(s_W + (64 + 2*ii    )*DD))[lane];
                    float2 w1v = ((const float2*)(s_W + (64 + 2*ii + 1)*DD))[lane];
                    acc0 += cx*w0.x + cy*w1v.x;
                    acc1 += cx*w0.y + cy*w1v.y;
                }
                float su = acc0 + acc1;
                float sq = acc0*acc0 + acc1*acc1;
                #pragma unroll
                for (int o = 16; o; o >>= 1) {
                    su += __shfl_xor_sync(0xffffffffu, su, o);
                    sq += __shfl_xor_sync(0xffffffffu, sq, o);
                }
                float mu  = su * (1.f/DD);
                float var = sq * (1.f/DD) - mu*mu;
                float rs  = rsqrtf(var + 1e-5f);
                float u0 = fmaxf((acc0 - mu)*rs*gj0 + btj0, 0.f);
                float u1 = fmaxf((acc1 - mu)*rs*gj1 + btj1, 0.f);
                x2.x += u0; x2.y += u1;
                ((float2*)g_x)[(size_t)row*32 + lane] = x2;
                ((float2*)g_agg)[(size_t)row*32 + lane] = make_float2(0.f, 0.f);
            }
            // cold path: dense z_l densify (z_l == 0 for these inputs)
            if (l < LL - 1 && g_zfl[l]) {
                for (int r = gid; r < NROWS; r += NTHREADS) {
                    if (!((g_xmask[r >> 5] >> (r & 31)) & 1)) {
                        for (int d = 0; d < DD; d++)
                            g_x[(size_t)r*DD + d] += g_zv[l][d];
                        atomicOr(&g_xmask[r >> 5], 1u << (r & 31));
                    }
                }
                for (int r = gid; r < TABW; r += NTHREADS)
                    g_tab[r] = 0xFFFFFFFFu;
            }
        }
        gridbar(s_base + 3 + 2*l);
    }

    // ---------------- score ------------------------------------------------
    if (blockIdx.x < BB*KK) {
        int b = blockIdx.x / KK, k = blockIdx.x % KK;
        if (tid < DD) {
            int ti = (b*KK + k)*3 + 1;
            int t  = clampi(g_b64 ? (int)((const long long*)batch)[ti]
                                  : ((const int*)batch)[ti], NN);
            int row = b*NN + t;
            float f = g_x[(size_t)row*DD + tid];
            if (g_zfl[LL-1] && !((g_xmask[row >> 5] >> (row & 31)) & 1))
                f += g_zv[LL-1][tid];
            s_feat[tid]      = f;
            s_feat[DD + tid] = g_query[b*DD + tid];
        }
        __syncthreads();
        if (tid < DD) {
            float acc = b1[tid];
            #pragma unroll 8
            for (int i = 0; i < 2*DD; i++) acc += s_feat[i] * w1[i*DD + tid];
            float h = fmaxf(acc, 0.f);
            s_hs[tid] = h * w2[tid];
        }
        __syncthreads();
        if (tid == 0) {
            float s = b2[0];
            for (int i = 0; i < DD; i++) s += s_hs[i];
            out[b*KK + k] = s;
        }
    }
}

// ---------------------------------------------------------------------------
extern "C" void kernel_launch(void* const* d_in, const int* in_sizes, int n_in,
                              void* d_out, int out_size) {
    const float* rel      = (const float*)d_in[0];
    const float* layer_w  = (const float*)d_in[1];
    const float* layer_b  = (const float*)d_in[2];
    const float* ln_g     = (const float*)d_in[3];
    const float* ln_b     = (const float*)d_in[4];
    const float* mlp_w1   = (const float*)d_in[5];
    const float* mlp_b1   = (const float*)d_in[6];
    const float* mlp_w2   = (const float*)d_in[7];
    const float* mlp_b2   = (const float*)d_in[8];
    const void*  batch    = d_in[9];
    const int*   edge_idx = (const int*)d_in[10];
    const int*   edge_typ = (const int*)d_in[11];
    float*       out      = (float*)d_out;

    k_main<<<GRID, BLK>>>(rel, layer_w, layer_b, ln_g, ln_b,
                          mlp_w1, mlp_b1, mlp_w2, mlp_b2,
                          batch, edge_idx, edge_typ, out);
}